// round 16
// baseline (speedup 1.0000x reference)
#include <cuda_runtime.h>
#include <cuda_bf16.h>
#include <cstdint>
#include <float.h>

// Problem constants (RaggedTopKGatingModule: N=524288, E=64, K=8)
#define E_EXPERTS 64
#define TOPK 8
#define BLOCK_A 256
#define TOK_PER_BLOCK 128                              // 2 lanes per token
#define SLOTS_PER_CHUNK (TOK_PER_BLOCK * TOPK)         // 1024
#define MAX_SLOTS (524288 * 8)
#define MAX_CHUNKS 4096
#define ROW_B 288                                      // 256B row + 2x16B pad
#define HALF_B 144

// Scratch (no allocation allowed; __device__ globals)
// packed per-slot: (expert_id << 8) | within_chunk_rank   (rank <= 127)
// hist/base are EXPERT-MAJOR [e*4096 + c] so kernel B is fully coalesced.
__device__ uint16_t g_pack[MAX_SLOTS];                 // 8 MB
__device__ int      g_chunk_hist[E_EXPERTS * MAX_CHUNKS];
__device__ int      g_chunk_base[E_EXPERTS * MAX_CHUNKS];

// 256-bit global load/store (sm_100+, PTX 8.7)
#define LDG256(p, r0,r1,r2,r3,r4,r5,r6,r7) \
    asm volatile("ld.global.nc.v8.f32 {%0,%1,%2,%3,%4,%5,%6,%7}, [%8];" \
        : "=f"(r0),"=f"(r1),"=f"(r2),"=f"(r3), \
          "=f"(r4),"=f"(r5),"=f"(r6),"=f"(r7) : "l"(p))

#define STG256(p, r0,r1,r2,r3,r4,r5,r6,r7) \
    asm volatile("st.global.v8.f32 [%0], {%1,%2,%3,%4,%5,%6,%7,%8};" \
        :: "l"(p), "f"(r0),"f"(r1),"f"(r2),"f"(r3), \
           "f"(r4),"f"(r5),"f"(r6),"f"(r7) : "memory")

// ---------------------------------------------------------------------------
// Kernel A: staged-smem pair-split top-8 (float/fma-pipe sort) + softmax
//           + logits copy (256-bit) + warp-local ordered ranking + assigns
// ---------------------------------------------------------------------------
__global__ __launch_bounds__(BLOCK_A, 6)
void topk_rank_kernel(const float* __restrict__ logits,
                      float* __restrict__ out_scores,
                      float* __restrict__ out_assign,
                      float* __restrict__ out_logits,
                      int n_tokens)
{
    __shared__ uint8_t  sh_stage[TOK_PER_BLOCK * ROW_B];   // 36 KB
    __shared__ uint64_t sh_e64[TOK_PER_BLOCK];             // 1 KB

    // phase-2-only tables overlaid into sh_stage (dead after phase-1 merge)
    int* sh_cnt  = (int*)sh_stage;                  // 8*64 ints = 2 KB
    int* sh_base = (int*)(sh_stage + 2048);         // 8*64 ints = 2 KB

    const int tid  = threadIdx.x;
    const int lane = tid & 31;
    const int warp = tid >> 5;
    const int chunk = blockIdx.x;
    const int tok_base = chunk * TOK_PER_BLOCK;

    // -------- Phase 0: 256-bit coalesced copy + padded smem staging --------
    {
        const size_t gbase = (size_t)tok_base * E_EXPERTS;
        const float* srcf = logits + gbase;
        float*       dstf = out_logits + gbase;
        #pragma unroll
        for (int k = 0; k < 4; ++k) {
            const int i8 = tid + k * BLOCK_A;          // 32B-unit index 0..1023
            float r0,r1,r2,r3,r4,r5,r6,r7;
            LDG256(srcf + (size_t)i8 * 8, r0,r1,r2,r3,r4,r5,r6,r7);
            STG256(dstf + (size_t)i8 * 8, r0,r1,r2,r3,r4,r5,r6,r7);
            const int tok = i8 >> 3, rem = i8 & 7;
            uint8_t* s = sh_stage + tok * ROW_B + (rem >> 2) * HALF_B
                                  + (rem & 3) * 32;
            *(float4*)(s)      = make_float4(r0, r1, r2, r3);
            *(float4*)(s + 16) = make_float4(r4, r5, r6, r7);
        }
    }
    __syncthreads();

    // -------- Phase 1: pair-split exact top-8 + softmax --------
    {
        const int lt   = tid >> 1;          // local token 0..127
        const int half = tid & 1;           // 0: experts 0-31, 1: 32-63
        const int t = tok_base + lt;
        uint8_t* myhalf = sh_stage + lt * ROW_B + half * HALF_B;

        float tv[TOPK];
        int   ti[TOPK];
        #pragma unroll
        for (int k = 0; k < TOPK; ++k) { tv[k] = -FLT_MAX; ti[k] = 0; }

        float s0 = 0.f, s1 = 0.f, s2 = 0.f, s3 = 0.f;

        #pragma unroll
        for (int j = 0; j < 8; ++j) {       // 32 experts per lane, from smem
            float4 q = *(const float4*)(myhalf + j * 16);
            float xs[4] = {q.x, q.y, q.z, q.w};
            s0 += __expf(q.x); s1 += __expf(q.y);
            s2 += __expf(q.z); s3 += __expf(q.w);
            #pragma unroll
            for (int u = 0; u < 4; ++u) {
                const int le = j * 4 + u;   // local expert id
                const float x = xs[u];
                // strict >: lowest-index-first on exact ties within half
                if (x > tv[TOPK - 1]) {
                    tv[TOPK - 1] = x; ti[TOPK - 1] = le;
                    #pragma unroll
                    for (int jj = TOPK - 1; jj > 0; --jj) {
                        if (tv[jj] > tv[jj - 1]) {
                            float tf = tv[jj]; tv[jj] = tv[jj - 1]; tv[jj - 1] = tf;
                            int   tt = ti[jj]; ti[jj] = ti[jj - 1]; ti[jj - 1] = tt;
                        }
                    }
                }
            }
        }

        // publish local top-8 IN PLACE into own (already consumed) region
        *(float4*)(myhalf +  0) = make_float4(tv[0], tv[1], tv[2], tv[3]);
        *(float4*)(myhalf + 16) = make_float4(tv[4], tv[5], tv[6], tv[7]);
        uint64_t idp = 0;
        #pragma unroll
        for (int k = 0; k < TOPK; ++k)
            idp |= (uint64_t)(uint8_t)(half * 32 + ti[k]) << (8 * k);
        *(uint64_t*)(myhalf + 32) = idp;

        const float mysum = (s0 + s1) + (s2 + s3);
        const float total = mysum + __shfl_xor_sync(0xffffffffu, mysum, 1);
        __syncwarp();                       // pair's STS visible

        if (!half) {
            const float*   KA = (const float*)(sh_stage + lt * ROW_B);
            const float*   KB = (const float*)(sh_stage + lt * ROW_B + HALF_B);
            const uint8_t* EA = sh_stage + lt * ROW_B + 32;
            const uint8_t* EB = sh_stage + lt * ROW_B + HALF_B + 32;
            const float inv = 1.0f / total;

            float sc[TOPK];
            uint64_t ep = 0;
            int i = 0, j = 0;
            #pragma unroll
            for (int k = 0; k < TOPK; ++k) {
                float ka = (i < 8) ? KA[i] : -FLT_MAX;
                float kb = (j < 8) ? KB[j] : -FLT_MAX;
                // ties -> even half (experts 0-31) = lower index first
                const bool takeA = (ka >= kb);
                const float   kk = takeA ? ka : kb;
                const uint8_t ee = takeA ? EA[i] : EB[j];
                i += takeA; j += !takeA;
                sc[k] = __expf(kk) * inv;
                ep |= (uint64_t)ee << (8 * k);
            }
            sh_e64[lt] = ep;
            STG256(out_scores + (size_t)t * TOPK,
                   sc[0], sc[1], sc[2], sc[3], sc[4], sc[5], sc[6], sc[7]);
        }
    }
    __syncthreads();                        // merge reads of stage complete

    // zero overlaid warp counters (stage region now dead)
    sh_cnt[tid] = 0; sh_cnt[tid + BLOCK_A] = 0;
    __syncthreads();

    // -------- Phase 2: warp-local ordered multisplit (slots 128w..128w+127) --
    const uint8_t* eb = (const uint8_t*)sh_e64;
    const unsigned lanemask_lt = (1u << lane) - 1u;
    int mye[4], myr[4];
    #pragma unroll
    for (int q = 0; q < 4; ++q) {
        const int slot = warp * 128 + q * 32 + lane;   // token-major order
        const int e = eb[slot];
        unsigned mask = __match_any_sync(0xffffffffu, e);
        const int lrank  = __popc(mask & lanemask_lt);
        const int leader = __ffs(mask) - 1;
        int prev = 0;
        if (lane == leader) {               // leader-only RMW: program-ordered
            prev = sh_cnt[warp * E_EXPERTS + e];
            sh_cnt[warp * E_EXPERTS + e] = prev + __popc(mask);
        }
        prev = __shfl_sync(0xffffffffu, prev, leader);
        mye[q] = e; myr[q] = prev + lrank;
        __syncwarp();                       // order leader STS before next round
    }
    __syncthreads();

    // single cross-warp scan; publish hist EXPERT-MAJOR
    if (tid < E_EXPERTS) {
        int run = 0;
        #pragma unroll
        for (int w = 0; w < 8; ++w) {
            sh_base[w * E_EXPERTS + tid] = run;
            run += sh_cnt[w * E_EXPERTS + tid];
        }
        g_chunk_hist[tid * MAX_CHUNKS + chunk] = run;
    }
    __syncthreads();

    const size_t slot_base = (size_t)chunk * SLOTS_PER_CHUNK;
    #pragma unroll
    for (int q = 0; q < 4; ++q) {
        const int s = warp * 128 + q * 32 + lane;
        const int rank = sh_base[warp * E_EXPERTS + mye[q]] + myr[q];  // <=127
        g_pack[slot_base + s] = (uint16_t)((mye[q] << 8) | rank);
        out_assign[slot_base + s] = (float)mye[q];     // coalesced 128B/warp
    }
}

// ---------------------------------------------------------------------------
// Kernel B: per-expert exclusive scan, expert-major -> int4 coalesced I/O
//           shfl-based: 2 block barriers total
// ---------------------------------------------------------------------------
__global__ void scan_kernel(float* __restrict__ out_counts, int n_chunks)
{
    __shared__ int warp_base[32];
    const int e    = blockIdx.x;
    const int c    = threadIdx.x;           // 0..1023
    const int lane = c & 31;
    const int w    = c >> 5;
    const int* __restrict__ hrow = g_chunk_hist + e * MAX_CHUNKS;
    int*       __restrict__ brow = g_chunk_base + e * MAX_CHUNKS;

    int4 v = *(const int4*)(hrow + 4 * c);  // coalesced 16B/thread
    const int quad = v.x + v.y + v.z + v.w;

    // inclusive warp scan of quad
    int incl = quad;
    #pragma unroll
    for (int off = 1; off < 32; off <<= 1) {
        int t = __shfl_up_sync(0xffffffffu, incl, off);
        if (lane >= off) incl += t;
    }
    if (lane == 31) warp_base[w] = incl;
    __syncthreads();

    if (w == 0) {
        int s = warp_base[lane];            // 32 warp totals
        int si = s;
        #pragma unroll
        for (int off = 1; off < 32; off <<= 1) {
            int t = __shfl_up_sync(0xffffffffu, si, off);
            if (lane >= off) si += t;
        }
        warp_base[lane] = si - s;           // exclusive warp base
        if (lane == 31) out_counts[e] = (float)si;   // grand total
    }
    __syncthreads();

    int run = warp_base[w] + incl - quad;   // exclusive thread base
    int4 b;
    b.x = run;            run += v.x;
    b.y = run;            run += v.y;
    b.z = run;            run += v.z;
    b.w = run;
    *(int4*)(brow + 4 * c) = b;             // coalesced 16B/thread
}

// ---------------------------------------------------------------------------
// Kernel C: final offsets only   (4 slots / thread; base gathers L2-resident)
// ---------------------------------------------------------------------------
__global__ __launch_bounds__(256, 8)
void offsets_kernel(float* __restrict__ out_offs, int n_quads)
{
    const int q = blockIdx.x * blockDim.x + threadIdx.x;
    if (q >= n_quads) return;
    const int idx = q * 4;
    const int chunk = idx >> 10;                    // / SLOTS_PER_CHUNK (1024)

    ushort4 p4 = *(const ushort4*)(g_pack + idx);
    const int* __restrict__ base = g_chunk_base + chunk;   // + e*4096

    float4 o;
    o.x = (float)(base[(p4.x >> 8) << 12] + (p4.x & 255));
    o.y = (float)(base[(p4.y >> 8) << 12] + (p4.y & 255));
    o.z = (float)(base[(p4.z >> 8) << 12] + (p4.z & 255));
    o.w = (float)(base[(p4.w >> 8) << 12] + (p4.w & 255));
    *(float4*)(out_offs + idx) = o;
}

// ---------------------------------------------------------------------------
extern "C" void kernel_launch(void* const* d_in, const int* in_sizes, int n_in,
                              void* d_out, int out_size)
{
    // inputs: [0]=expert_counts(E), [1]=assignments(N*K), [2]=offsets(N*K), [3]=logits(N*E)
    const float* logits = (const float*)d_in[3];
    const int n_tokens = in_sizes[3] / E_EXPERTS;       // 524288
    const int n_slots  = n_tokens * TOPK;               // 4194304
    const int n_chunks = n_tokens / TOK_PER_BLOCK;      // 4096

    float* out = (float*)d_out;
    // layout: counts[E] | scores[N*K] | assign[N*K] | offs[N*K] | logits[N*E]
    float* out_counts = out;
    float* out_scores = out + E_EXPERTS;
    float* out_assign = out_scores + (size_t)n_slots;
    float* out_offs   = out_assign + (size_t)n_slots;
    float* out_logits = out_offs   + (size_t)n_slots;

    topk_rank_kernel<<<n_chunks, BLOCK_A>>>(logits, out_scores, out_assign,
                                            out_logits, n_tokens);
    scan_kernel<<<E_EXPERTS, 1024>>>(out_counts, n_chunks);
    const int n_quads = n_slots / 4;
    offsets_kernel<<<(n_quads + 255) / 256, 256>>>(out_offs, n_quads);
}